// round 14
// baseline (speedup 1.0000x reference)
#include <cuda_runtime.h>

#define N_NODES 50000
#define N_EDGES 1600000
#define N_EPAD  (N_EDGES + N_NODES)   // room for per-row even padding
#define BATCH   4
#define T_STEPS 50
#define DT      0.02f

// ---------------- static scratch (no allocations allowed) ----------------
__device__ int    g_hist[N_NODES];
__device__ int    g_row_start[N_NODES + 1];     // padded-even segments
__device__ int    g_cursor[N_NODES];
__device__ int4   g_epairs[N_EPAD / 2];         // 2 edges per int4 {s0,w0,s1,w1}
                                                // zero-init: pad slots stay w=0
__device__ float4 g_rates[2][N_NODES];          // ping-pong rate buffers
__device__ float4 g_v[N_NODES];                 // membrane state
__device__ float  g_alpha[N_NODES];

// ---------------- packed-math helpers ----------------
__device__ __forceinline__ void gather_fma(const float4* rp, float w,
                                           unsigned long long& a01,
                                           unsigned long long& a23) {
    unsigned long long r01, r23, ww;
    asm volatile("{\n\t"
        ".reg .f32 ra,rb,rc,rd;\n\t"
        "ld.global.nc.v4.f32 {ra,rb,rc,rd}, [%2];\n\t"
        "mov.b64 %0, {ra,rb};\n\t"
        "mov.b64 %1, {rc,rd};\n\t}"
        : "=l"(r01), "=l"(r23) : "l"(rp));
    asm("mov.b64 %0, {%1,%1};" : "=l"(ww) : "f"(w));
    asm("fma.rn.f32x2 %0, %1, %2, %0;" : "+l"(a01) : "l"(r01), "l"(ww));
    asm("fma.rn.f32x2 %0, %1, %2, %0;" : "+l"(a23) : "l"(r23), "l"(ww));
}

// streaming (evict-first) edge-pair load — keeps L1 for the rate array
__device__ __forceinline__ int4 ldcs_i4(const int4* p) {
    int4 v;
    asm volatile("ld.global.cs.v4.b32 {%0,%1,%2,%3}, [%4];"
                 : "=r"(v.x), "=r"(v.y), "=r"(v.z), "=r"(v.w) : "l"(p));
    return v;
}

// ---------------- preprocessing ----------------

// zero the histogram (must precede the atomic pass)
__global__ void zero_kernel() {
    int n = blockIdx.x * blockDim.x + threadIdx.x;
    if (n < N_NODES) g_hist[n] = 0;
}

// fused: edge histogram + node-state init (independent writes)
__global__ void hist_init_kernel(const int*   __restrict__ tgt,
                                 const float* __restrict__ bias,
                                 const float* __restrict__ tau) {
    int e = blockIdx.x * blockDim.x + threadIdx.x;
    if (e < N_EDGES) atomicAdd(&g_hist[tgt[e]], 1);
    if (e < N_NODES) {
        float b = bias[e];
        g_v[e] = make_float4(b, b, b, b);
        float r = fmaxf(b, 0.0f);
        g_rates[0][e] = make_float4(r, r, r, r);
        float tt = fmaxf(tau[e], DT);
        g_alpha[e] = DT / tt;
    }
}

// Exclusive scan over PADDED-EVEN degrees -> 16B-aligned pair segments
__global__ void scan_kernel() {
    __shared__ int s[1024];
    int tid = threadIdx.x;
    const int chunk = (N_NODES + 1023) / 1024;   // 49
    int beg = tid * chunk;
    int end = min(beg + chunk, N_NODES);
    int sum = 0;
    for (int i = beg; i < end; i++) sum += (g_hist[i] + 1) & ~1;
    s[tid] = sum;
    __syncthreads();
    for (int off = 1; off < 1024; off <<= 1) {
        int v = (tid >= off) ? s[tid - off] : 0;
        __syncthreads();
        s[tid] += v;
        __syncthreads();
    }
    int prefix = (tid > 0) ? s[tid - 1] : 0;
    for (int i = beg; i < end; i++) {
        g_row_start[i] = prefix;
        g_cursor[i]    = prefix;
        prefix += (g_hist[i] + 1) & ~1;
    }
    if (tid == 0) g_row_start[N_NODES] = s[1023];
}

// Counting-sort edges into padded CSR; pad slots remain zero (never written).
__global__ void scatter_kernel(const int*   __restrict__ src,
                               const int*   __restrict__ tgt,
                               const float* __restrict__ sign,
                               const float* __restrict__ cnt,
                               const float* __restrict__ str) {
    int e = blockIdx.x * blockDim.x + threadIdx.x;
    if (e >= N_EDGES) return;
    float w = sign[e] * fmaxf(cnt[e], 0.0f) * fmaxf(str[e], 0.0f);
    int pos = atomicAdd(&g_cursor[tgt[e]], 1);
    ((int2*)g_epairs)[pos] = make_int2(src[e], __float_as_int(w));
}

// ---------------- hot loop: one kernel per timestep ----------------
// 8 lanes per row, 32 rows per 256-thread block. Each lane processes edge
// PAIRS (one LDG.128 record = 2 edges) with packed f32x2 FMA accumulation.
// Loop steps 16 pairs (= mean row) with depth-2 unroll: no dead predicated
// issues on the average row, MLP>=2 on long rows.
__global__ void __launch_bounds__(256)
step_kernel(const float* __restrict__ x,
            float*       __restrict__ out,
            const float* __restrict__ bias,
            int t, int parity) {
    __shared__ float s_acc[BATCH][32];

    int sub = threadIdx.x & 7;        // lane within 8-lane row group
    int grp = threadIdx.x >> 3;       // row group within block
    int row = blockIdx.x * 32 + grp;

    const float4* __restrict__ rin = g_rates[parity];

    unsigned long long a01 = 0ull, a23 = 0ull;   // packed {f32,f32} accumulators
    if (row < N_NODES) {
        int pbeg = g_row_start[row] >> 1;        // segments even => exact
        int pend = g_row_start[row + 1] >> 1;
        for (int p0 = pbeg; p0 < pend; p0 += 16) {
#pragma unroll
            for (int j = 0; j < 2; j++) {
                int pp = p0 + sub + 8 * j;
                if (pp < pend) {
                    int4 rec = ldcs_i4(&g_epairs[pp]);
                    gather_fma(&rin[rec.x], __int_as_float(rec.y), a01, a23);
                    gather_fma(&rin[rec.z], __int_as_float(rec.w), a01, a23);
                }
            }
        }
    }
    float4 acc;
    asm("mov.b64 {%0,%1}, %2;" : "=f"(acc.x), "=f"(acc.y) : "l"(a01));
    asm("mov.b64 {%0,%1}, %2;" : "=f"(acc.z), "=f"(acc.w) : "l"(a23));

#pragma unroll
    for (int off = 4; off; off >>= 1) {
        acc.x += __shfl_down_sync(0xffffffffu, acc.x, off);
        acc.y += __shfl_down_sync(0xffffffffu, acc.y, off);
        acc.z += __shfl_down_sync(0xffffffffu, acc.z, off);
        acc.w += __shfl_down_sync(0xffffffffu, acc.w, off);
    }
    if (sub == 0) {
        s_acc[0][grp] = acc.x;
        s_acc[1][grp] = acc.y;
        s_acc[2][grp] = acc.z;
        s_acc[3][grp] = acc.w;
    }
    __syncthreads();

    // epilogue: 128 threads cover (batch, row) fully coalesced
    if (threadIdx.x < BATCH * 32) {
        int b = threadIdx.x >> 5;
        int r = threadIdx.x & 31;
        int row2 = blockIdx.x * 32 + r;
        if (row2 < N_NODES) {
            float a   = g_alpha[row2];
            float bs  = bias[row2];
            float ab  = s_acc[b][r];
            long long idx = (long long)(b * T_STEPS + t) * N_NODES + row2;
            float xv  = x[idx];
            float* vf = (float*)&g_v[row2];
            float v   = vf[b];
            float vn  = v + a * (bs + ab + xv - v);
            vf[b] = vn;
            float rl = fmaxf(vn, 0.f);
            float* routf = (float*)(g_rates[parity ^ 1]);
            routf[row2 * 4 + b] = rl;
            out[idx] = rl;
        }
    }
}

// ---------------- launch ----------------
extern "C" void kernel_launch(void* const* d_in, const int* in_sizes, int n_in,
                              void* d_out, int out_size) {
    const float* x    = (const float*)d_in[0];
    const float* bias = (const float*)d_in[1];
    const float* tau  = (const float*)d_in[2];
    const float* sign = (const float*)d_in[3];
    const float* cnt  = (const float*)d_in[4];
    const float* str  = (const float*)d_in[5];
    const int*   src  = (const int*)  d_in[6];
    const int*   tgt  = (const int*)  d_in[7];
    float*       out  = (float*)d_out;

    zero_kernel<<<(N_NODES + 255) / 256, 256>>>();
    hist_init_kernel<<<(N_EDGES + 255) / 256, 256>>>(tgt, bias, tau);
    scan_kernel<<<1, 1024>>>();
    scatter_kernel<<<(N_EDGES + 255) / 256, 256>>>(src, tgt, sign, cnt, str);

    const int step_blocks = (N_NODES + 31) / 32;   // 1563
    for (int t = 0; t < T_STEPS; t++) {
        step_kernel<<<step_blocks, 256>>>(x, out, bias, t, t & 1);
    }
}